// round 4
// baseline (speedup 1.0000x reference)
#include <cuda_runtime.h>
#include <math.h>
#include <stdint.h>

// ---------------- problem constants ----------------
#define HID 256          // H
#define NHEAD 4
#define DHEAD 64
#define BATCH 256        // B
#define SEQL 128         // L
#define TT 256           // T
#define TS 255           // T-1 scan steps
#define RROWS (TS*BATCH) // 65280
#define NNODE (BATCH*SEQL) // 32768
#define G3 768           // 3*H

// ---------------- device scratch (static, no allocs) ----------------
__device__ int   g_is64;
__device__ float g_XW[NNODE*HID];            // nodes @ gat_w
__device__ float g_ASD[NNODE*8];             // a_src(4), a_dst(4) per node
__device__ float g_ROUT[NNODE*HID];          // route_outputs (b,l,h)
__device__ float g_ROUTT[BATCH*HID*SEQL];    // (b,h,l) transposed
__device__ float g_H0[BATCH*HID];            // hidden0
__device__ float g_WIHT[257*G3];             // W_ih^T (k,j)
__device__ float g_W3[256*256*4];            // packed W_hh: [k][f]{r,z,n,0}
__device__ float g_F1T[512*512];             // fc1_w^T
__device__ float g_GI[RROWS*G3];             // precomputed input gates
__device__ float g_RIN[RROWS*512];           // [h_t | weighted] rows
__device__ float g_FC1[RROWS*512];           // relu(fc1)

// ---------------- small utility kernels ----------------
__global__ void k_detect(const int* __restrict__ t) {
    if (threadIdx.x == 0) {
        int all0 = 1;
        for (int q = 1; q < 256; q += 2) if (t[q] != 0) { all0 = 0; break; }
        g_is64 = all0;   // 1 => trg_id is int64 on disk
    }
}

__global__ void k_memset(float* p, int n) {
    int i = blockIdx.x * blockDim.x + threadIdx.x;
    if (i < n) p[i] = 0.f;
}

// out[c*rows + r] = in[r*cols + c]
__global__ void k_transpose(const float* __restrict__ in, float* __restrict__ out,
                            int rows, int cols) {
    int idx = blockIdx.x * blockDim.x + threadIdx.x;
    if (idx >= rows * cols) return;
    int r = idx / cols, c = idx - r * cols;
    out[c * rows + r] = in[idx];
}

// pack W_hh (768x256 row-major) -> g_W3[k][f] = {whh[f][k], whh[256+f][k], whh[512+f][k], 0}
__global__ void k_packw3(const float* __restrict__ whh) {
    int idx = blockIdx.x * 256 + threadIdx.x;   // 65536
    int k = idx >> 8, f = idx & 255;
    float4 v;
    v.x = whh[f * 256 + k];
    v.y = whh[(256 + f) * 256 + k];
    v.z = whh[(512 + f) * 256 + k];
    v.w = 0.f;
    ((float4*)g_W3)[k * 256 + f] = v;
}

// ---------------- GAT: a_src / a_dst projections ----------------
__global__ void k_asd(const float* __restrict__ asrc, const float* __restrict__ adst) {
    __shared__ float ss[HID], sd[HID];
    int t = threadIdx.x;
    ss[t] = asrc[t]; sd[t] = adst[t];
    __syncthreads();
    int gid = blockIdx.x * 256 + t;
    int n = gid >> 2, h = gid & 3;
    const float* x = &g_XW[n * HID + h * DHEAD];
    const float* cs = &ss[h * DHEAD];
    const float* cd = &sd[h * DHEAD];
    float s = 0.f, d = 0.f;
#pragma unroll 8
    for (int q = 0; q < DHEAD; q++) { float v = x[q]; s += v * cs[q]; d += v * cd[q]; }
    g_ASD[n * 8 + h] = s;
    g_ASD[n * 8 + 4 + h] = d;
}

// ---------------- GAT aggregate + residual + LayerNorm ----------------
__global__ void k_gat(const float* __restrict__ emb, const float* __restrict__ bias,
                      const float* __restrict__ gamma, const float* __restrict__ beta) {
    int i = blockIdx.x;              // node id
    int j = threadIdx.x;             // feature
    int h = j >> 6;                  // head
    int l = i & (SEQL - 1);
    float ad = g_ASD[i * 8 + 4 + h];
    bool v0 = (l > 0), v1 = (l < SEQL - 1);
    float e0 = -1e30f, e1 = -1e30f;
    if (v0) { float e = g_ASD[(i - 1) * 8 + h] + ad; e0 = e > 0.f ? e : 0.2f * e; }
    if (v1) { float e = g_ASD[(i + 1) * 8 + h] + ad; e1 = e > 0.f ? e : 0.2f * e; }
    float emax = fmaxf(e0, e1);
    float x0 = v0 ? expf(e0 - emax) : 0.f;
    float x1 = v1 ? expf(e1 - emax) : 0.f;
    float inv = 1.f / (x0 + x1 + 1e-16f);
    float a0 = x0 * inv, a1 = x1 * inv;
    float val = bias[j] + emb[(long long)i * HID + j];
    if (v0) val += a0 * g_XW[(i - 1) * HID + j];
    if (v1) val += a1 * g_XW[(i + 1) * HID + j];
    __shared__ float red[HID];
    red[j] = val; __syncthreads();
    for (int s = 128; s > 0; s >>= 1) { if (j < s) red[j] += red[j + s]; __syncthreads(); }
    float mean = red[0] * (1.f / HID); __syncthreads();
    float dv = val - mean;
    red[j] = dv * dv; __syncthreads();
    for (int s = 128; s > 0; s >>= 1) { if (j < s) red[j] += red[j + s]; __syncthreads(); }
    float var = red[0] * (1.f / HID);
    g_ROUT[(long long)i * HID + j] = dv * rsqrtf(var + 1e-5f) * gamma[j] + beta[j];
}

__global__ void k_hidden0() {
    int b = blockIdx.x, j = threadIdx.x;
    const float* p = &g_ROUT[(long long)b * SEQL * HID + j];
    float s = 0.f;
    for (int l = 0; l < SEQL; l++) s += p[l * HID];
    g_H0[b * HID + j] = s * (1.f / SEQL);
}

// (b,l,h) -> (b,h,l)
__global__ void k_routt() {
    __shared__ float tile[32][33];
    int b = blockIdx.z;
    int h0 = blockIdx.x * 32, l0 = blockIdx.y * 32;
    int x = threadIdx.x, y = threadIdx.y;
    const float* in = &g_ROUT[(long long)b * SEQL * HID];
    float* out = &g_ROUTT[(long long)b * HID * SEQL];
    for (int yy = y; yy < 32; yy += 8) tile[yy][x] = in[(l0 + yy) * HID + h0 + x];
    __syncthreads();
    for (int yy = y; yy < 32; yy += 8) out[(h0 + yy) * SEQL + l0 + x] = tile[x][yy];
}

// ---------------- fp32 tiled SGEMM (used for XW / scores / weighted) ----------------
__global__ __launch_bounds__(256, 2) void k_sgemm(
    int M, int N, int K,
    const float* __restrict__ A, int lda, long long sA,
    const float* __restrict__ B, int ldb, long long sB,
    float* __restrict__ C, int ldc, long long sC,
    const int* __restrict__ maskPtr, int maskStride,
    float alpha)
{
    __shared__ float As[8][128];
    __shared__ float Bs[8][128];
    const float* Ab = A + (long long)blockIdx.z * sA;
    const float* Bb = B + (long long)blockIdx.z * sB;
    float* Cb = C + (long long)blockIdx.z * sC;
    int m0 = blockIdx.y * 128, n0 = blockIdx.x * 128;
    int tid = threadIdx.x, tx = tid & 15, ty = tid >> 4;
    float acc[8][8];
#pragma unroll
    for (int i = 0; i < 8; i++)
#pragma unroll
        for (int j = 0; j < 8; j++) acc[i][j] = 0.f;

    int rowL = tid >> 1, kq = (tid & 1) * 4;
    int grow = m0 + rowL; if (grow > M - 1) grow = M - 1;
    const float* Arow = Ab + (long long)grow * lda;
    int kB = tid >> 5, nq = (tid & 31) * 4;

    for (int k0 = 0; k0 < K; k0 += 8) {
        float4 av = *(const float4*)(Arow + k0 + kq);
        As[kq + 0][rowL] = av.x; As[kq + 1][rowL] = av.y;
        As[kq + 2][rowL] = av.z; As[kq + 3][rowL] = av.w;
        *(float4*)&Bs[kB][nq] = *(const float4*)(Bb + (long long)(k0 + kB) * ldb + n0 + nq);
        __syncthreads();
#pragma unroll
        for (int kk = 0; kk < 8; kk++) {
            float a[8], b[8];
            *(float4*)&a[0] = *(const float4*)&As[kk][ty * 4];
            *(float4*)&a[4] = *(const float4*)&As[kk][64 + ty * 4];
            *(float4*)&b[0] = *(const float4*)&Bs[kk][tx * 4];
            *(float4*)&b[4] = *(const float4*)&Bs[kk][64 + tx * 4];
#pragma unroll
            for (int i = 0; i < 8; i++)
#pragma unroll
                for (int j = 0; j < 8; j++) acc[i][j] += a[i] * b[j];
        }
        __syncthreads();
    }
#pragma unroll
    for (int i = 0; i < 8; i++) {
        int mloc = (i < 4) ? ty * 4 + i : 64 + ty * 4 + (i - 4);
        int m = m0 + mloc;
        if (m >= M) continue;
#pragma unroll
        for (int j = 0; j < 8; j++) {
            int nloc = (j < 4) ? tx * 4 + j : 64 + tx * 4 + (j - 4);
            int n = n0 + nloc;
            float v = acc[i][j] * alpha;
            if (maskPtr && maskPtr[(long long)blockIdx.z * maskStride + n] == 0) v = -1e9f;
            Cb[(long long)m * ldc + n] = v;
        }
    }
}

// ---------------- tf32 tensor-core GEMM (128x128 tile, BK=16, m16n8k8) ----------------
__device__ __forceinline__ uint32_t f2tf(float x) {
    uint32_t r; asm("cvt.rna.tf32.f32 %0, %1;" : "=r"(r) : "f"(x)); return r;
}

// C[M,N] = A[M,K] @ B[K,N]  (+bias[n]) (+rowScal[m]*rowVec[n]) [relu]
// A rows optionally gathered via gth (int32/int64 auto per g_is64).
// Requires M%128==0, N%128==0, K%16==0.
__global__ __launch_bounds__(256, 2) void k_tgemm(
    int M, int N, int K,
    const float* __restrict__ A, int lda,
    const float* __restrict__ B, int ldb,
    float* __restrict__ C, int ldc,
    const void* __restrict__ gth,
    const float* __restrict__ rowScal, const float* __restrict__ rowVec,
    const float* __restrict__ bias, int doRelu)
{
    __shared__ uint32_t As[128][20];   // stride 20: conflict-free fragment loads
    __shared__ uint32_t Bs[16][136];   // stride 136: conflict-free fragment loads

    int m0 = blockIdx.y * 128, n0 = blockIdx.x * 128;
    int tid = threadIdx.x;

    // A staging assignment: thread -> (row, 8 consecutive k)
    int rloc = tid >> 1;
    int cA = (tid & 1) * 8;
    int grow = m0 + rloc;
    const float* Arow;
    if (gth) {
        long long gr = g_is64 ? ((const long long*)gth)[grow]
                              : (long long)((const int*)gth)[grow];
        Arow = A + gr * (long long)lda;
    } else {
        Arow = A + (long long)grow * lda;
    }
    // B staging: thread -> (k row, 4 consecutive n); covers k and k+8
    int kb = tid >> 5, cB = (tid & 31) * 4;

    int wid = tid >> 5, lane = tid & 31;
    int wm = wid & 3, wn = wid >> 2;        // warp grid 4 x 2
    int mBase = wm * 32, nBase = wn * 64;
    int grp = lane >> 2, thr = lane & 3;

    float acc[2][8][4];
#pragma unroll
    for (int mt = 0; mt < 2; mt++)
#pragma unroll
        for (int nt = 0; nt < 8; nt++)
#pragma unroll
            for (int q = 0; q < 4; q++) acc[mt][nt][q] = 0.f;

    for (int k0 = 0; k0 < K; k0 += 16) {
        float4 av0 = *(const float4*)(Arow + k0 + cA);
        float4 av1 = *(const float4*)(Arow + k0 + cA + 4);
        As[rloc][cA + 0] = f2tf(av0.x); As[rloc][cA + 1] = f2tf(av0.y);
        As[rloc][cA + 2] = f2tf(av0.z); As[rloc][cA + 3] = f2tf(av0.w);
        As[rloc][cA + 4] = f2tf(av1.x); As[rloc][cA + 5] = f2tf(av1.y);
        As[rloc][cA + 6] = f2tf(av1.z); As[rloc][cA + 7] = f2tf(av1.w);

        float4 bv0 = *(const float4*)(B + (long long)(k0 + kb) * ldb + n0 + cB);
        float4 bv1 = *(const float4*)(B + (long long)(k0 + kb + 8) * ldb + n0 + cB);
        Bs[kb][cB + 0] = f2tf(bv0.x); Bs[kb][cB + 1] = f2tf(bv0.y);
        Bs[kb][cB + 2] = f2tf(bv0.z); Bs[kb][cB + 3] = f2tf(bv0.w);
        Bs[kb + 8][cB + 0] = f2tf(bv1.x); Bs[kb + 8][cB + 1] = f2tf(bv1.y);
        Bs[kb + 8][cB + 2] = f2tf(bv1.z); Bs[kb + 8][cB + 3] = f2tf(bv1.w);
        __syncthreads();

#pragma unroll
        for (int kk = 0; kk < 16; kk += 8) {
            uint32_t af[2][4];
#pragma unroll
            for (int mt = 0; mt < 2; mt++) {
                int row = mBase + mt * 16 + grp;
                af[mt][0] = As[row][kk + thr];
                af[mt][1] = As[row + 8][kk + thr];
                af[mt][2] = As[row][kk + thr + 4];
                af[mt][3] = As[row + 8][kk + thr + 4];
            }
#pragma unroll
            for (int nt = 0; nt < 8; nt++) {
                int col = nBase + nt * 8 + grp;
                uint32_t b0 = Bs[kk + thr][col];
                uint32_t b1 = Bs[kk + thr + 4][col];
#pragma unroll
                for (int mt = 0; mt < 2; mt++) {
                    float* c = acc[mt][nt];
                    asm volatile(
                        "mma.sync.aligned.m16n8k8.row.col.f32.tf32.tf32.f32 "
                        "{%0,%1,%2,%3},{%4,%5,%6,%7},{%8,%9},{%0,%1,%2,%3};"
                        : "+f"(c[0]), "+f"(c[1]), "+f"(c[2]), "+f"(c[3])
                        : "r"(af[mt][0]), "r"(af[mt][1]), "r"(af[mt][2]), "r"(af[mt][3]),
                          "r"(b0), "r"(b1));
                }
            }
        }
        __syncthreads();
    }

#pragma unroll
    for (int mt = 0; mt < 2; mt++) {
        int r0 = m0 + mBase + mt * 16 + grp;
        int r1 = r0 + 8;
        float s0 = rowScal ? rowScal[r0] : 0.f;
        float s1 = rowScal ? rowScal[r1] : 0.f;
#pragma unroll
        for (int nt = 0; nt < 8; nt++) {
            int cb = n0 + nBase + nt * 8 + thr * 2;
            float v00 = acc[mt][nt][0], v01 = acc[mt][nt][1];
            float v10 = acc[mt][nt][2], v11 = acc[mt][nt][3];
            if (bias) {
                float b0 = bias[cb], b1 = bias[cb + 1];
                v00 += b0; v01 += b1; v10 += b0; v11 += b1;
            }
            if (rowScal) {
                float w0 = rowVec[cb], w1 = rowVec[cb + 1];
                v00 += s0 * w0; v01 += s0 * w1;
                v10 += s1 * w0; v11 += s1 * w1;
            }
            if (doRelu) {
                v00 = fmaxf(v00, 0.f); v01 = fmaxf(v01, 0.f);
                v10 = fmaxf(v10, 0.f); v11 = fmaxf(v11, 0.f);
            }
            C[(long long)r0 * ldc + cb] = v00;
            C[(long long)r0 * ldc + cb + 1] = v01;
            C[(long long)r1 * ldc + cb] = v10;
            C[(long long)r1 * ldc + cb + 1] = v11;
        }
    }
}

// ---------------- GRU step v2: tile 32 feats x 16 batches, packed W3 ----------------
// hprev: row stride ldh_in; hnew: row stride ldh_out (writes h into RIN left half)
__global__ __launch_bounds__(256) void k_gru2(
    const float* __restrict__ hprev, int ldh_in,
    const float* __restrict__ gi,
    const float* __restrict__ bhh,
    float* __restrict__ hnew, int ldh_out)
{
    __shared__ float hs[256][18];
    int t = threadIdx.x;
    int f0 = blockIdx.x * 32, b0 = blockIdx.y * 16;
    for (int idx = t; idx < 4096; idx += 256) {
        int b = idx >> 8, k = idx & 255;
        hs[k][b] = hprev[(long long)(b0 + b) * ldh_in + k];
    }
    __syncthreads();

    int f = f0 + (t & 31);
    int bq = t >> 5;                       // 0..7 -> 2 batches each
    const float4* Wv = (const float4*)g_W3 + f;
    float ar0 = 0.f, az0 = 0.f, an0 = 0.f;
    float ar1 = 0.f, az1 = 0.f, an1 = 0.f;
#pragma unroll 4
    for (int k = 0; k < 256; k++) {
        float4 w = Wv[k * 256];
        float2 h2 = *(const float2*)&hs[k][bq * 2];
        ar0 += w.x * h2.x; az0 += w.y * h2.x; an0 += w.z * h2.x;
        ar1 += w.x * h2.y; az1 += w.y * h2.y; an1 += w.z * h2.y;
    }
    float br = bhh[f], bz = bhh[256 + f], bn = bhh[512 + f];
#pragma unroll
    for (int bb = 0; bb < 2; bb++) {
        int bl = bq * 2 + bb, b = b0 + bl;
        const float* g = gi + (long long)b * G3;
        float ar = bb ? ar1 : ar0, az = bb ? az1 : az0, an = bb ? an1 : an0;
        float r = 1.f / (1.f + expf(-(g[f] + br + ar)));
        float z = 1.f / (1.f + expf(-(g[256 + f] + bz + az)));
        float n = tanhf(g[512 + f] + r * (bn + an));
        float hp = hs[f][bl];
        hnew[(long long)b * ldh_out + f] = (1.f - z) * n + z * hp;
    }
}

// ---------------- softmax over L=128 (one warp per (t,b)) ----------------
__global__ void k_softmax(float* __restrict__ base, const int* __restrict__ mask) {
    int gid = blockIdx.x * blockDim.x + threadIdx.x;
    int w = gid >> 5, lane = gid & 31;
    if (w >= RROWS) return;
    float* row = base + (long long)w * SEQL;
    int b = w & (BATCH - 1);
    float v[4];
#pragma unroll
    for (int q = 0; q < 4; q++) v[q] = row[lane + 32 * q];
    float mx = fmaxf(fmaxf(v[0], v[1]), fmaxf(v[2], v[3]));
    for (int o = 16; o > 0; o >>= 1) mx = fmaxf(mx, __shfl_xor_sync(0xffffffffu, mx, o));
    float s = 0.f;
#pragma unroll
    for (int q = 0; q < 4; q++) { v[q] = expf(v[q] - mx); s += v[q]; }
    for (int o = 16; o > 0; o >>= 1) s += __shfl_xor_sync(0xffffffffu, s, o);
    float inv = 1.f / s;
    const int* mk = mask + b * SEQL;
#pragma unroll
    for (int q = 0; q < 4; q++) {
        int l = lane + 32 * q;
        float a = v[q] * inv;
        row[l] = mk[l] ? a : 0.f;
    }
}

// ---------------- fc2 + sigmoid (one warp per row) ----------------
__global__ void k_fc2(const float* __restrict__ w2, const float* __restrict__ b2,
                      float* __restrict__ outr) {
    int gid = blockIdx.x * blockDim.x + threadIdx.x;
    int w = gid >> 5, lane = gid & 31;
    if (w >= RROWS) return;
    const float* row = &g_FC1[(long long)w * 512];
    float s = 0.f;
#pragma unroll
    for (int q = 0; q < 16; q++) s += row[lane + 32 * q] * w2[lane + 32 * q];
    for (int o = 16; o > 0; o >>= 1) s += __shfl_xor_sync(0xffffffffu, s, o);
    if (lane == 0) outr[w] = 1.f / (1.f + expf(-(s + b2[0])));
}

// ---------------- host launcher ----------------
extern "C" void kernel_launch(void* const* d_in, const int* in_sizes, int n_in,
                              void* d_out, int out_size) {
    const float* route_emb = (const float*)d_in[0];
    const int*   trg_id    = (const int*)  d_in[2];
    const float* trg_rate  = (const float*)d_in[3];
    const int*   mask      = (const int*)  d_in[5];
    const float* emb_id    = (const float*)d_in[6];
    const float* gat_w     = (const float*)d_in[7];
    const float* a_src     = (const float*)d_in[8];
    const float* a_dst     = (const float*)d_in[9];
    const float* gat_bias  = (const float*)d_in[10];
    const float* ln_g      = (const float*)d_in[11];
    const float* ln_b      = (const float*)d_in[12];
    const float* w_ih      = (const float*)d_in[13];
    const float* w_hh      = (const float*)d_in[14];
    const float* b_ih      = (const float*)d_in[15];
    const float* b_hh      = (const float*)d_in[16];
    const float* fc1w      = (const float*)d_in[17];
    const float* fc1b      = (const float*)d_in[18];
    const float* fc2w      = (const float*)d_in[19];
    const float* fc2b      = (const float*)d_in[20];
    float* out = (float*)d_out;

    float *XW, *ROUT, *ROUTT, *H0, *WIHT, *F1T, *GI, *RIN, *FC1;
    cudaGetSymbolAddress((void**)&XW,   g_XW);
    cudaGetSymbolAddress((void**)&ROUT, g_ROUT);
    cudaGetSymbolAddress((void**)&ROUTT,g_ROUTT);
    cudaGetSymbolAddress((void**)&H0,   g_H0);
    cudaGetSymbolAddress((void**)&WIHT, g_WIHT);
    cudaGetSymbolAddress((void**)&F1T,  g_F1T);
    cudaGetSymbolAddress((void**)&GI,   g_GI);
    cudaGetSymbolAddress((void**)&RIN,  g_RIN);
    cudaGetSymbolAddress((void**)&FC1,  g_FC1);

    const long long IDSZ = (long long)TT * BATCH * SEQL;   // 8388608

    // dtype sniff + zero the t=0 output rows
    k_detect<<<1, 32>>>(trg_id);
    k_memset<<<(BATCH * SEQL + 255) / 256, 256>>>(out, BATCH * SEQL);
    k_memset<<<1, 256>>>(out + IDSZ, BATCH);

    // weight transposes / packs
    k_transpose<<<(768 * 257 + 255) / 256, 256>>>(w_ih, WIHT, 768, 257);
    k_packw3<<<256, 256>>>(w_hh);
    k_transpose<<<(512 * 512 + 255) / 256, 256>>>(fc1w, F1T, 512, 512);

    // --- GAT (fp32 for precision of outputs_id) ---
    k_sgemm<<<dim3(2, 256, 1), 256>>>(NNODE, HID, HID,
        route_emb, HID, 0, gat_w, HID, 0, XW, HID, 0, nullptr, 0, 1.f);
    k_asd<<<NNODE * 4 / 256, 256>>>(a_src, a_dst);
    k_gat<<<NNODE, HID>>>(route_emb, gat_bias, ln_g, ln_b);
    k_hidden0<<<BATCH, HID>>>();
    k_routt<<<dim3(8, 4, BATCH), dim3(32, 8)>>>();

    // --- GI = gather(emb_id) @ W_ih[:, :256]^T + rate*W_ih[:,256] + b_ih (tf32) ---
    k_tgemm<<<dim3(6, 510), 256>>>(RROWS, G3, HID,
        emb_id, HID, WIHT, G3, GI, G3,
        (const void*)trg_id, trg_rate, WIHT + 256 * G3, b_ih, 0);

    // --- sequential GRU scan; h_t written into RIN left half (stride 512) ---
    for (int t = 0; t < TS; t++) {
        const float* hp = t ? RIN + (long long)(t - 1) * BATCH * 512 : H0;
        int ldin = t ? 512 : HID;
        k_gru2<<<dim3(8, 16), 256>>>(hp, ldin, GI + (long long)t * BATCH * G3,
                                     b_hh, RIN + (long long)t * BATCH * 512, 512);
    }

    // --- scores (fp32): S[t,b,l] = (1/16) * h[t,b,:]·ROUT[b,l,:] -> d_out ---
    k_sgemm<<<dim3(1, 2, BATCH), 256>>>(TS, SEQL, HID,
        RIN, BATCH * 512, 512,                 // A: h rows, t-stride B*512, b-offset 512
        ROUTT, SEQL, (long long)HID * SEQL,
        out + (long long)BATCH * SEQL, BATCH * SEQL, SEQL,
        mask, SEQL, 0.0625f);

    // --- softmax over l, masked zeros, in place in d_out ---
    k_softmax<<<RROWS / 4, 128>>>(out + (long long)BATCH * SEQL, mask);

    // --- weighted[t,b,h] = attn[t,b,:] @ ROUT[b,:,h] -> RIN right half (fp32) ---
    k_sgemm<<<dim3(2, 2, BATCH), 256>>>(TS, HID, SEQL,
        out + (long long)BATCH * SEQL, BATCH * SEQL, SEQL,
        ROUT, HID, (long long)SEQL * HID,
        RIN + 256, BATCH * 512, 512,
        nullptr, 0, 1.f);

    // --- rate head: fc1 relu (tf32) then fc2 sigmoid ---
    k_tgemm<<<dim3(4, 510), 256>>>(RROWS, 512, 512,
        RIN, 512, F1T, 512, FC1, 512,
        nullptr, nullptr, nullptr, fc1b, 1);
    k_fc2<<<(RROWS * 32 + 255) / 256, 256>>>(fc2w, fc2b, out + IDSZ + BATCH);
}

// round 5
// speedup vs baseline: 2.4966x; 2.4966x over previous
#include <cuda_runtime.h>
#include <cuda_bf16.h>
#include <math.h>
#include <stdint.h>

// ---------------- problem constants ----------------
#define HID 256          // H
#define NHEAD 4
#define DHEAD 64
#define BATCH 256        // B
#define SEQL 128         // L
#define TT 256           // T
#define TS 255           // T-1 scan steps
#define RROWS (TS*BATCH) // 65280
#define NNODE (BATCH*SEQL) // 32768
#define G3 768           // 3*H

// ---------------- device scratch (static, no allocs) ----------------
__device__ int   g_is64;
__device__ float g_XW[NNODE*HID];
__device__ float g_ASD[NNODE*8];
__device__ float g_ROUT[NNODE*HID];
__device__ float g_ROUTT[BATCH*HID*SEQL];
__device__ float g_H0[BATCH*HID];
__device__ float g_WIHT[257*G3];
__device__ float g_F1T[512*512];
__device__ float g_GI[RROWS*G3];
__device__ float g_RIN[RROWS*512];           // [h_t | weighted] rows
__device__ float g_FC1[RROWS*512];
__device__ uint4 g_WPK[24576];               // W_hh packed bf16 MMA fragments (393KB)

// ---------------- small utility kernels ----------------
__global__ void k_detect(const int* __restrict__ t) {
    if (threadIdx.x == 0) {
        int all0 = 1;
        for (int q = 1; q < 256; q += 2) if (t[q] != 0) { all0 = 0; break; }
        g_is64 = all0;
    }
}

__global__ void k_memset(float* p, int n) {
    int i = blockIdx.x * blockDim.x + threadIdx.x;
    if (i < n) p[i] = 0.f;
}

__global__ void k_transpose(const float* __restrict__ in, float* __restrict__ out,
                            int rows, int cols) {
    int idx = blockIdx.x * blockDim.x + threadIdx.x;
    if (idx >= rows * cols) return;
    int r = idx / cols, c = idx - r * cols;
    out[c * rows + r] = in[idx];
}

// pack W_hh (768x256 row-major) into bf16 m16n8k16 B-fragment order.
// index = ((w*16 + c)*6 + tp)*32 + lane ; per uint4: {b0_t0,b1_t0,b0_t1,b1_t1}
__global__ void k_packbf(const float* __restrict__ whh) {
    int gid = blockIdx.x * 256 + threadIdx.x;     // 0..24575
    int lane = gid & 31;
    int r1 = gid >> 5;
    int tp = r1 % 6;
    int r2 = r1 / 6;
    int c = r2 & 15, w = r2 >> 4;
    int grp = lane >> 2, thr = lane & 3;
    int j0 = w * 96 + (2 * tp) * 8 + grp;
    int j1 = j0 + 8;
    int kb = c * 16 + 2 * thr;
    const float* W0 = whh + j0 * 256;
    const float* W1 = whh + j1 * 256;
#define PK(a,b) ((uint32_t)__bfloat16_as_ushort(__float2bfloat16(a)) | \
                 ((uint32_t)__bfloat16_as_ushort(__float2bfloat16(b)) << 16))
    uint4 v;
    v.x = PK(W0[kb],     W0[kb + 1]);
    v.y = PK(W0[kb + 8], W0[kb + 9]);
    v.z = PK(W1[kb],     W1[kb + 1]);
    v.w = PK(W1[kb + 8], W1[kb + 9]);
#undef PK
    g_WPK[gid] = v;
}

// ---------------- GAT: a_src / a_dst projections ----------------
__global__ void k_asd(const float* __restrict__ asrc, const float* __restrict__ adst) {
    __shared__ float ss[HID], sd[HID];
    int t = threadIdx.x;
    ss[t] = asrc[t]; sd[t] = adst[t];
    __syncthreads();
    int gid = blockIdx.x * 256 + t;
    int n = gid >> 2, h = gid & 3;
    const float* x = &g_XW[n * HID + h * DHEAD];
    const float* cs = &ss[h * DHEAD];
    const float* cd = &sd[h * DHEAD];
    float s = 0.f, d = 0.f;
#pragma unroll 8
    for (int q = 0; q < DHEAD; q++) { float v = x[q]; s += v * cs[q]; d += v * cd[q]; }
    g_ASD[n * 8 + h] = s;
    g_ASD[n * 8 + 4 + h] = d;
}

// ---------------- GAT aggregate + residual + LayerNorm ----------------
__global__ void k_gat(const float* __restrict__ emb, const float* __restrict__ bias,
                      const float* __restrict__ gamma, const float* __restrict__ beta) {
    int i = blockIdx.x;
    int j = threadIdx.x;
    int h = j >> 6;
    int l = i & (SEQL - 1);
    float ad = g_ASD[i * 8 + 4 + h];
    bool v0 = (l > 0), v1 = (l < SEQL - 1);
    float e0 = -1e30f, e1 = -1e30f;
    if (v0) { float e = g_ASD[(i - 1) * 8 + h] + ad; e0 = e > 0.f ? e : 0.2f * e; }
    if (v1) { float e = g_ASD[(i + 1) * 8 + h] + ad; e1 = e > 0.f ? e : 0.2f * e; }
    float emax = fmaxf(e0, e1);
    float x0 = v0 ? expf(e0 - emax) : 0.f;
    float x1 = v1 ? expf(e1 - emax) : 0.f;
    float inv = 1.f / (x0 + x1 + 1e-16f);
    float a0 = x0 * inv, a1 = x1 * inv;
    float val = bias[j] + emb[(long long)i * HID + j];
    if (v0) val += a0 * g_XW[(i - 1) * HID + j];
    if (v1) val += a1 * g_XW[(i + 1) * HID + j];
    __shared__ float red[HID];
    red[j] = val; __syncthreads();
    for (int s = 128; s > 0; s >>= 1) { if (j < s) red[j] += red[j + s]; __syncthreads(); }
    float mean = red[0] * (1.f / HID); __syncthreads();
    float dv = val - mean;
    red[j] = dv * dv; __syncthreads();
    for (int s = 128; s > 0; s >>= 1) { if (j < s) red[j] += red[j + s]; __syncthreads(); }
    float var = red[0] * (1.f / HID);
    g_ROUT[(long long)i * HID + j] = dv * rsqrtf(var + 1e-5f) * gamma[j] + beta[j];
}

__global__ void k_hidden0() {
    int b = blockIdx.x, j = threadIdx.x;
    const float* p = &g_ROUT[(long long)b * SEQL * HID + j];
    float s = 0.f;
    for (int l = 0; l < SEQL; l++) s += p[l * HID];
    g_H0[b * HID + j] = s * (1.f / SEQL);
}

// (b,l,h) -> (b,h,l)
__global__ void k_routt() {
    __shared__ float tile[32][33];
    int b = blockIdx.z;
    int h0 = blockIdx.x * 32, l0 = blockIdx.y * 32;
    int x = threadIdx.x, y = threadIdx.y;
    const float* in = &g_ROUT[(long long)b * SEQL * HID];
    float* out = &g_ROUTT[(long long)b * HID * SEQL];
    for (int yy = y; yy < 32; yy += 8) tile[yy][x] = in[(l0 + yy) * HID + h0 + x];
    __syncthreads();
    for (int yy = y; yy < 32; yy += 8) out[(h0 + yy) * SEQL + l0 + x] = tile[x][yy];
}

// ---------------- generic tiled SGEMM (128x128x8, 8x8/thread) ----------------
__global__ __launch_bounds__(256, 2) void k_sgemm(
    int M, int N, int K,
    const float* __restrict__ A, int lda, long long sA,
    const float* __restrict__ B, int ldb, long long sB,
    float* __restrict__ C, int ldc, long long sC,
    const void* __restrict__ gth,
    const float* __restrict__ rowScal, const float* __restrict__ rowVec,
    const float* __restrict__ bias,
    const int* __restrict__ maskPtr, int maskStride,
    float alpha, int doRelu)
{
    __shared__ float As[8][128];
    __shared__ float Bs[8][128];
    const float* Ab = A + (long long)blockIdx.z * sA;
    const float* Bb = B + (long long)blockIdx.z * sB;
    float* Cb = C + (long long)blockIdx.z * sC;
    int m0 = blockIdx.y * 128, n0 = blockIdx.x * 128;
    int tid = threadIdx.x, tx = tid & 15, ty = tid >> 4;
    float acc[8][8];
#pragma unroll
    for (int i = 0; i < 8; i++)
#pragma unroll
        for (int j = 0; j < 8; j++) acc[i][j] = 0.f;

    int rowL = tid >> 1, kq = (tid & 1) * 4;
    int grow = m0 + rowL; if (grow > M - 1) grow = M - 1;
    const float* Arow;
    if (gth) {
        long long gr = g_is64 ? ((const long long*)gth)[grow]
                              : (long long)((const int*)gth)[grow];
        Arow = Ab + gr * (long long)lda;
    } else {
        Arow = Ab + (long long)grow * lda;
    }
    int kB = tid >> 5, nq = (tid & 31) * 4;

    for (int k0 = 0; k0 < K; k0 += 8) {
        float4 av = *(const float4*)(Arow + k0 + kq);
        As[kq + 0][rowL] = av.x; As[kq + 1][rowL] = av.y;
        As[kq + 2][rowL] = av.z; As[kq + 3][rowL] = av.w;
        *(float4*)&Bs[kB][nq] = *(const float4*)(Bb + (long long)(k0 + kB) * ldb + n0 + nq);
        __syncthreads();
#pragma unroll
        for (int kk = 0; kk < 8; kk++) {
            float a[8], b[8];
            *(float4*)&a[0] = *(const float4*)&As[kk][ty * 4];
            *(float4*)&a[4] = *(const float4*)&As[kk][64 + ty * 4];
            *(float4*)&b[0] = *(const float4*)&Bs[kk][tx * 4];
            *(float4*)&b[4] = *(const float4*)&Bs[kk][64 + tx * 4];
#pragma unroll
            for (int i = 0; i < 8; i++)
#pragma unroll
                for (int j = 0; j < 8; j++) acc[i][j] += a[i] * b[j];
        }
        __syncthreads();
    }
#pragma unroll
    for (int i = 0; i < 8; i++) {
        int mloc = (i < 4) ? ty * 4 + i : 64 + ty * 4 + (i - 4);
        int m = m0 + mloc;
        if (m >= M) continue;
        float rs = rowScal ? rowScal[m] : 0.f;
#pragma unroll
        for (int j = 0; j < 8; j++) {
            int nloc = (j < 4) ? tx * 4 + j : 64 + tx * 4 + (j - 4);
            int n = n0 + nloc;
            float v = acc[i][j] * alpha;
            if (bias)    v += bias[n];
            if (rowScal) v += rs * rowVec[n];
            if (doRelu)  v = fmaxf(v, 0.f);
            if (maskPtr && maskPtr[(long long)blockIdx.z * maskStride + n] == 0) v = -1e9f;
            Cb[(long long)m * ldc + n] = v;
        }
    }
}

// ---------------- MUFU-free sigmoid (exp2 poly + Newton reciprocal) ----------------
__device__ __forceinline__ float fast_sigmoid(float x) {
    x = fminf(fmaxf(x, -87.f), 87.f);
    float t = x * -1.44269504f;              // e^-x = 2^t
    float r = rintf(t);
    float f = t - r;                          // |f| <= 0.5
    float p = 1.33335581e-3f;
    p = fmaf(p, f, 9.61812910e-3f);
    p = fmaf(p, f, 5.55041086e-2f);
    p = fmaf(p, f, 2.40226507e-1f);
    p = fmaf(p, f, 6.93147181e-1f);
    p = fmaf(p, f, 1.f);
    int i = (int)r;
    float E = __int_as_float((i + 127) << 23) * p;   // e^-x
    float u = 1.f + E;
    float y = __int_as_float(0x7EF311C3 - __float_as_int(u));  // ~1/u
    y = y * fmaf(-u, y, 2.f);
    y = y * fmaf(-u, y, 2.f);
    y = y * fmaf(-u, y, 2.f);
    return y;
}

__device__ __forceinline__ void mma16816(float* c, uint32_t a0, uint32_t a1,
                                         uint32_t a2, uint32_t a3,
                                         uint32_t b0, uint32_t b1) {
    asm volatile(
        "mma.sync.aligned.m16n8k16.row.col.f32.bf16.bf16.f32 "
        "{%0,%1,%2,%3},{%4,%5,%6,%7},{%8,%9},{%0,%1,%2,%3};"
        : "+f"(c[0]), "+f"(c[1]), "+f"(c[2]), "+f"(c[3])
        : "r"(a0), "r"(a1), "r"(a2), "r"(a3), "r"(b0), "r"(b1));
}

__device__ __forceinline__ uint32_t sm2u(const void* p) {
    return (uint32_t)__cvta_generic_to_shared(p);
}

// ---------------- fused GRU scan: ONE kernel, 16 blocks x 16 batches ----------------
// smem layout (bytes): hs bf16 h [16][136]u32 @0 (8704) ; hfs fp32 h [16][264] @8704
// (16896) ; ghs [16][776] @25600 (49664) ; gis [16][772] @75264 (49408) = 124672
#define SCAN_SMEM 124672
__global__ __launch_bounds__(256) void k_scan(const float* __restrict__ giAll,
                                              const float* __restrict__ bhh,
                                              const float* __restrict__ h0,
                                              float* __restrict__ rin)
{
    extern __shared__ char sm[];
    uint32_t* hs = (uint32_t*)sm;                        // [16][136] bf16x2
    __nv_bfloat16* hsh = (__nv_bfloat16*)sm;             // [16][272] halves
    float* hfs = (float*)(sm + 8704);                    // [16][264]
    float* ghs = (float*)(sm + 25600);                   // [16][776]
    float* gis = (float*)(sm + 75264);                   // [16][772]

    int tid = threadIdx.x;
    int wid = tid >> 5, lane = tid & 31, grp = lane >> 2, thr = lane & 3;
    int b0 = blockIdx.x * 16;

    // init h from h0
    for (int idx = tid; idx < 16 * 256; idx += 256) {
        int b = idx >> 8, f = idx & 255;
        float h = h0[(b0 + b) * 256 + f];
        hfs[b * 264 + f] = h;
        hsh[b * 272 + f] = __float2bfloat16(h);
    }
    float brr = bhh[tid], bzz = bhh[256 + tid], bnn = bhh[512 + tid];

    // prefetch gi for t=0
    {
        const float* srcb = giAll + (size_t)b0 * G3;
#pragma unroll
        for (int q = 0; q < 12; q++) {
            int idx = q * 256 + tid;
            int b = idx / 192, c = idx - b * 192;
            const float* s = srcb + (size_t)b * G3 + c * 4;
            asm volatile("cp.async.cg.shared.global [%0], [%1], 16;"
                         :: "r"(sm2u(&gis[b * 772 + c * 4])), "l"(s));
        }
        asm volatile("cp.async.commit_group;" ::: "memory");
    }
    __syncthreads();

    const uint4* wpw = g_WPK + wid * 96 * 32 + lane;

    for (int t = 0; t < TS; t++) {
        // ---- MMA phase: gh[16 x 768] = h_bf16 @ W^T ----
        float acc[12][4];
#pragma unroll
        for (int tt = 0; tt < 12; tt++)
#pragma unroll
            for (int q = 0; q < 4; q++) acc[tt][q] = 0.f;

#pragma unroll
        for (int c = 0; c < 16; c++) {
            uint32_t a0 = hs[grp * 136 + c * 8 + thr];
            uint32_t a1 = hs[(grp + 8) * 136 + c * 8 + thr];
            uint32_t a2 = hs[grp * 136 + c * 8 + thr + 4];
            uint32_t a3 = hs[(grp + 8) * 136 + c * 8 + thr + 4];
#pragma unroll
            for (int tp = 0; tp < 6; tp++) {
                uint4 bv = wpw[(c * 6 + tp) * 32];
                mma16816(acc[2 * tp],     a0, a1, a2, a3, bv.x, bv.y);
                mma16816(acc[2 * tp + 1], a0, a1, a2, a3, bv.z, bv.w);
            }
        }
#pragma unroll
        for (int tt = 0; tt < 12; tt++) {
            int col = wid * 96 + tt * 8 + 2 * thr;
            *(float2*)&ghs[grp * 776 + col]       = make_float2(acc[tt][0], acc[tt][1]);
            *(float2*)&ghs[(grp + 8) * 776 + col] = make_float2(acc[tt][2], acc[tt][3]);
        }
        asm volatile("cp.async.wait_group 0;" ::: "memory");
        __syncthreads();

        // ---- gate phase ----
        float* rrow = rin + ((size_t)t * BATCH + b0) * 512;
#pragma unroll 2
        for (int b = 0; b < 16; b++) {
            float r = fast_sigmoid(gis[b * 772 + tid] + ghs[b * 776 + tid] + brr);
            float z = fast_sigmoid(gis[b * 772 + 256 + tid] + ghs[b * 776 + 256 + tid] + bzz);
            float na = gis[b * 772 + 512 + tid] + r * (ghs[b * 776 + 512 + tid] + bnn);
            float n = fmaf(2.f, fast_sigmoid(2.f * na), -1.f);   // tanh(na)
            float hp = hfs[b * 264 + tid];
            float h = n + z * (hp - n);
            hfs[b * 264 + tid] = h;
            hsh[b * 272 + tid] = __float2bfloat16(h);
            rrow[b * 512 + tid] = h;
        }
        __syncthreads();

        // ---- prefetch gi for t+1 ----
        if (t < TS - 1) {
            const float* srcb = giAll + ((size_t)(t + 1) * BATCH + b0) * G3;
#pragma unroll
            for (int q = 0; q < 12; q++) {
                int idx = q * 256 + tid;
                int b = idx / 192, c = idx - b * 192;
                const float* s = srcb + (size_t)b * G3 + c * 4;
                asm volatile("cp.async.cg.shared.global [%0], [%1], 16;"
                             :: "r"(sm2u(&gis[b * 772 + c * 4])), "l"(s));
            }
            asm volatile("cp.async.commit_group;" ::: "memory");
        }
    }
}

// ---------------- softmax over L=128 (one warp per (t,b)) ----------------
__global__ void k_softmax(float* __restrict__ base, const int* __restrict__ mask) {
    int gid = blockIdx.x * blockDim.x + threadIdx.x;
    int w = gid >> 5, lane = gid & 31;
    if (w >= RROWS) return;
    float* row = base + (long long)w * SEQL;
    int b = w & (BATCH - 1);
    float v[4];
#pragma unroll
    for (int q = 0; q < 4; q++) v[q] = row[lane + 32 * q];
    float mx = fmaxf(fmaxf(v[0], v[1]), fmaxf(v[2], v[3]));
    for (int o = 16; o > 0; o >>= 1) mx = fmaxf(mx, __shfl_xor_sync(0xffffffffu, mx, o));
    float s = 0.f;
#pragma unroll
    for (int q = 0; q < 4; q++) { v[q] = expf(v[q] - mx); s += v[q]; }
    for (int o = 16; o > 0; o >>= 1) s += __shfl_xor_sync(0xffffffffu, s, o);
    float inv = 1.f / s;
    const int* mk = mask + b * SEQL;
#pragma unroll
    for (int q = 0; q < 4; q++) {
        int l = lane + 32 * q;
        float a = v[q] * inv;
        row[l] = mk[l] ? a : 0.f;
    }
}

// ---------------- fc2 + sigmoid (one warp per row) ----------------
__global__ void k_fc2(const float* __restrict__ w2, const float* __restrict__ b2,
                      float* __restrict__ outr) {
    int gid = blockIdx.x * blockDim.x + threadIdx.x;
    int w = gid >> 5, lane = gid & 31;
    if (w >= RROWS) return;
    const float* row = &g_FC1[(long long)w * 512];
    float s = 0.f;
#pragma unroll
    for (int q = 0; q < 16; q++) s += row[lane + 32 * q] * w2[lane + 32 * q];
    for (int o = 16; o > 0; o >>= 1) s += __shfl_xor_sync(0xffffffffu, s, o);
    if (lane == 0) outr[w] = 1.f / (1.f + expf(-(s + b2[0])));
}

// ---------------- host launcher ----------------
extern "C" void kernel_launch(void* const* d_in, const int* in_sizes, int n_in,
                              void* d_out, int out_size) {
    const float* route_emb = (const float*)d_in[0];
    const int*   trg_id    = (const int*)  d_in[2];
    const float* trg_rate  = (const float*)d_in[3];
    const int*   mask      = (const int*)  d_in[5];
    const float* emb_id    = (const float*)d_in[6];
    const float* gat_w     = (const float*)d_in[7];
    const float* a_src     = (const float*)d_in[8];
    const float* a_dst     = (const float*)d_in[9];
    const float* gat_bias  = (const float*)d_in[10];
    const float* ln_g      = (const float*)d_in[11];
    const float* ln_b      = (const float*)d_in[12];
    const float* w_ih      = (const float*)d_in[13];
    const float* w_hh      = (const float*)d_in[14];
    const float* b_ih      = (const float*)d_in[15];
    const float* b_hh      = (const float*)d_in[16];
    const float* fc1w      = (const float*)d_in[17];
    const float* fc1b      = (const float*)d_in[18];
    const float* fc2w      = (const float*)d_in[19];
    const float* fc2b      = (const float*)d_in[20];
    float* out = (float*)d_out;

    float *XW, *ROUT, *ROUTT, *H0, *WIHT, *F1T, *GI, *RIN, *FC1;
    cudaGetSymbolAddress((void**)&XW,   g_XW);
    cudaGetSymbolAddress((void**)&ROUT, g_ROUT);
    cudaGetSymbolAddress((void**)&ROUTT,g_ROUTT);
    cudaGetSymbolAddress((void**)&H0,   g_H0);
    cudaGetSymbolAddress((void**)&WIHT, g_WIHT);
    cudaGetSymbolAddress((void**)&F1T,  g_F1T);
    cudaGetSymbolAddress((void**)&GI,   g_GI);
    cudaGetSymbolAddress((void**)&RIN,  g_RIN);
    cudaGetSymbolAddress((void**)&FC1,  g_FC1);

    cudaFuncSetAttribute(k_scan, cudaFuncAttributeMaxDynamicSharedMemorySize, SCAN_SMEM);

    const long long IDSZ = (long long)TT * BATCH * SEQL;   // 8388608

    // launches 1-4: detect, WIHT transpose, output zeroing
    k_detect<<<1, 32>>>(trg_id);
    k_transpose<<<(768 * 257 + 255) / 256, 256>>>(w_ih, WIHT, 768, 257);
    k_memset<<<(BATCH * SEQL + 255) / 256, 256>>>(out, BATCH * SEQL);
    k_memset<<<1, 256>>>(out + IDSZ, BATCH);

    // launch 5 (ncu target): GI = gather(emb_id) @ W_ih^T + rate*col + b_ih
    k_sgemm<<<dim3(6, 510, 1), 256>>>(RROWS, G3, HID,
        emb_id, HID, 0, WIHT, G3, 0, GI, G3, 0,
        (const void*)trg_id, trg_rate, WIHT + 256 * G3, b_ih,
        nullptr, 0, 1.f, 0);

    // weight packs / transposes
    k_packbf<<<96, 256>>>(w_hh);
    k_transpose<<<(512 * 512 + 255) / 256, 256>>>(fc1w, F1T, 512, 512);

    // --- GAT ---
    k_sgemm<<<dim3(2, 256, 1), 256>>>(NNODE, HID, HID,
        route_emb, HID, 0, gat_w, HID, 0, XW, HID, 0,
        nullptr, nullptr, nullptr, nullptr, nullptr, 0, 1.f, 0);
    k_asd<<<NNODE * 4 / 256, 256>>>(a_src, a_dst);
    k_gat<<<NNODE, HID>>>(route_emb, gat_bias, ln_g, ln_b);
    k_hidden0<<<BATCH, HID>>>();
    k_routt<<<dim3(8, 4, BATCH), dim3(32, 8)>>>();

    // --- fused GRU scan: one kernel, writes h into RIN left half ---
    k_scan<<<16, 256, SCAN_SMEM>>>(GI, b_hh, H0, RIN);

    // --- scores: S[t,b,l] = (1/16) * h[t,b,:]·ROUT[b,l,:] -> d_out ---
    k_sgemm<<<dim3(1, 2, BATCH), 256>>>(TS, SEQL, HID,
        RIN, BATCH * 512, 512,
        ROUTT, SEQL, (long long)HID * SEQL,
        out + (long long)BATCH * SEQL, BATCH * SEQL, SEQL,
        nullptr, nullptr, nullptr, nullptr,
        mask, SEQL, 0.0625f, 0);

    // --- softmax over l, masked zeros, in place in d_out ---
    k_softmax<<<RROWS / 4, 128>>>(out + (long long)BATCH * SEQL, mask);

    // --- weighted[t,b,h] = attn[t,b,:] @ ROUT[b,:,h] -> RIN right half ---
    k_sgemm<<<dim3(2, 2, BATCH), 256>>>(TS, HID, SEQL,
        out + (long long)BATCH * SEQL, BATCH * SEQL, SEQL,
        ROUT, HID, (long long)SEQL * HID,
        RIN + 256, BATCH * 512, 512,
        nullptr, nullptr, nullptr, nullptr, nullptr, 0, 1.f, 0);

    // --- rate head: fc1 relu then fc2 sigmoid ---
    k_sgemm<<<dim3(4, 510, 1), 256>>>(RROWS, 512, 512,
        RIN, 512, 0, F1T, 512, 0, FC1, 512, 0,
        nullptr, nullptr, nullptr, fc1b, nullptr, 0, 1.f, 1);
    k_fc2<<<(RROWS * 32 + 255) / 256, 256>>>(fc2w, fc2b, out + IDSZ + BATCH);
}